// round 2
// baseline (speedup 1.0000x reference)
#include <cuda_runtime.h>
#include <cstdint>

#define TE 32
#define NTHREADS 256

// scatter-sum scratch (N_NODES * D_MSG), zeroed every call
__device__ float g_agg[50000 * 128];

__device__ __forceinline__ unsigned long long pk2(float lo, float hi) {
    unsigned long long r;
    asm("mov.b64 %0, {%1, %2};" : "=l"(r) : "f"(lo), "f"(hi));
    return r;
}
__device__ __forceinline__ void upk2(unsigned long long v, float& lo, float& hi) {
    asm("mov.b64 {%0, %1}, %2;" : "=f"(lo), "=f"(hi) : "l"(v));
}
// packed dual-fp32 FMA (FFMA2) — only reachable via PTX on sm_103a
__device__ __forceinline__ unsigned long long fma2(unsigned long long a,
                                                   unsigned long long b,
                                                   unsigned long long c) {
    unsigned long long d;
    asm("fma.rn.f32x2 %0, %1, %2, %3;" : "=l"(d) : "l"(a), "l"(b), "l"(c));
    return d;
}

__global__ void zero_agg_kernel(float* agg, int n4) {
    int i = blockIdx.x * blockDim.x + threadIdx.x;
    if (i < n4) ((float4*)agg)[i] = make_float4(0.f, 0.f, 0.f, 0.f);
}

// Fused 2-layer MLP over 32-row tiles.
// IS_EDGE:  rows are edges;  A = [x[tgt] | x[src]],  result atomically added to agg[tgt].
// !IS_EDGE: rows are nodes;  A = [x[n]   | agg[n] ], result stored to out[n].
// Layer1: [TE,256] @ W1[256,512] (+b1, relu)  -> processed in 128-col chunks through SMEM
// Layer2: chunk    @ W2[512,128] (+b2)        -> accumulated in registers (f32x2 pairs)
template <bool IS_EDGE>
__global__ __launch_bounds__(NTHREADS)
void mlp_kernel(const float* __restrict__ x,
                const float* __restrict__ second,
                const int* __restrict__ eidx,
                const float* __restrict__ W1, const float* __restrict__ b1,
                const float* __restrict__ W2, const float* __restrict__ b2,
                float* __restrict__ out,
                int M, int E) {
    extern __shared__ float smem[];
    float* As = smem;               // [TE][256]
    float* Ws = As + TE * 256;      // [32][128]
    float* Hs = Ws + 32 * 128;      // [TE][128]
    int* sA = (int*)(Hs + TE * 128);
    int* sB = sA + TE;
    int* sV = sB + TE;

    const int tid = threadIdx.x;
    const int rowbase = blockIdx.x * TE;

    if (tid < TE) {
        int r = rowbase + tid;
        int valid = (r < M) ? 1 : 0;
        int na = 0, nb = 0;
        if (valid) {
            if (IS_EDGE) {
                nb = eidx[r];              // row 0: source j
                na = eidx[E + r];          // row 1: target i
            } else {
                na = r; nb = r;
            }
        }
        sA[tid] = na; sB[tid] = nb; sV[tid] = valid;
    }
    __syncthreads();

    // gather A: cols [0,128) = x[na], cols [128,256) = x[nb] (edge) / second[nb] (node)
    for (int i = tid; i < TE * 64; i += NTHREADS) {
        int r = i >> 6, q = i & 63;
        float4 v = make_float4(0.f, 0.f, 0.f, 0.f);
        if (sV[r]) {
            if (q < 32) {
                v = *(const float4*)&x[(size_t)sA[r] * 128 + q * 4];
            } else {
                const float* src = IS_EDGE ? x : second;
                v = *(const float4*)&src[(size_t)sB[r] * 128 + (q - 32) * 4];
            }
        }
        *(float4*)&As[r * 256 + q * 4] = v;
    }
    // (As reads happen after the first Ws-load __syncthreads below)

    const int rg = tid >> 5;
    const int lane = tid & 31;
    const int r0 = rg * 4;      // 8 row-groups * 4 rows
    const int c0 = lane * 4;    // 32 col-groups * 4 cols

    unsigned long long msg[8];  // 4 rows x 2 f32x2 pairs (4 cols)
    {
        float4 bb = *(const float4*)&b2[c0];
        unsigned long long p0 = pk2(bb.x, bb.y), p1 = pk2(bb.z, bb.w);
#pragma unroll
        for (int i = 0; i < 4; i++) { msg[2 * i] = p0; msg[2 * i + 1] = p1; }
    }

    for (int nc = 0; nc < 512; nc += 128) {
        // ---- layer 1 chunk: hc[TE,128] = A @ W1[:, nc:nc+128] + b1 ----
        unsigned long long hc[8];
        {
            float4 bb = *(const float4*)&b1[nc + c0];
            unsigned long long p0 = pk2(bb.x, bb.y), p1 = pk2(bb.z, bb.w);
#pragma unroll
            for (int i = 0; i < 4; i++) { hc[2 * i] = p0; hc[2 * i + 1] = p1; }
        }
        for (int kk = 0; kk < 256; kk += 32) {
            __syncthreads();
            for (int i = tid; i < 1024; i += NTHREADS) {
                int k = i >> 5, cq = i & 31;
                *(float4*)&Ws[k * 128 + cq * 4] =
                    *(const float4*)&W1[(size_t)(kk + k) * 512 + nc + cq * 4];
            }
            __syncthreads();
#pragma unroll
            for (int k = 0; k < 32; k++) {
                float4 w = *(float4*)&Ws[k * 128 + c0];
                unsigned long long w0 = pk2(w.x, w.y), w1 = pk2(w.z, w.w);
#pragma unroll
                for (int i = 0; i < 4; i++) {
                    float a = As[(r0 + i) * 256 + kk + k];
                    unsigned long long aa = pk2(a, a);
                    hc[2 * i]     = fma2(aa, w0, hc[2 * i]);
                    hc[2 * i + 1] = fma2(aa, w1, hc[2 * i + 1]);
                }
            }
        }
        __syncthreads();
        // relu -> Hs
#pragma unroll
        for (int i = 0; i < 4; i++) {
            float l0, h0, l1, h1;
            upk2(hc[2 * i], l0, h0);
            upk2(hc[2 * i + 1], l1, h1);
            float4 v;
            v.x = fmaxf(l0, 0.f); v.y = fmaxf(h0, 0.f);
            v.z = fmaxf(l1, 0.f); v.w = fmaxf(h1, 0.f);
            *(float4*)&Hs[(r0 + i) * 128 + c0] = v;
        }
        // ---- layer 2: msg += relu(hc) @ W2[nc:nc+128, :] ----
        for (int kk = 0; kk < 128; kk += 32) {
            __syncthreads();
            for (int i = tid; i < 1024; i += NTHREADS) {
                int k = i >> 5, cq = i & 31;
                *(float4*)&Ws[k * 128 + cq * 4] =
                    *(const float4*)&W2[(size_t)(nc + kk + k) * 128 + cq * 4];
            }
            __syncthreads();
#pragma unroll
            for (int k = 0; k < 32; k++) {
                float4 w = *(float4*)&Ws[k * 128 + c0];
                unsigned long long w0 = pk2(w.x, w.y), w1 = pk2(w.z, w.w);
#pragma unroll
                for (int i = 0; i < 4; i++) {
                    float a = Hs[(r0 + i) * 128 + kk + k];
                    unsigned long long aa = pk2(a, a);
                    msg[2 * i]     = fma2(aa, w0, msg[2 * i]);
                    msg[2 * i + 1] = fma2(aa, w1, msg[2 * i + 1]);
                }
            }
        }
    }

    // emit
#pragma unroll
    for (int i = 0; i < 4; i++) {
        int r = r0 + i;
        if (!sV[r]) continue;
        float l0, h0, l1, h1;
        upk2(msg[2 * i], l0, h0);
        upk2(msg[2 * i + 1], l1, h1);
        if (IS_EDGE) {
            float* dst = &out[(size_t)sA[r] * 128 + c0];
            atomicAdd(dst + 0, l0);
            atomicAdd(dst + 1, h0);
            atomicAdd(dst + 2, l1);
            atomicAdd(dst + 3, h1);
        } else {
            float4 v;
            v.x = l0; v.y = h0; v.z = l1; v.w = h1;
            *(float4*)&out[(size_t)(rowbase + r) * 128 + c0] = v;
        }
    }
}

extern "C" void kernel_launch(void* const* d_in, const int* in_sizes, int n_in,
                              void* d_out, int out_size) {
    const float* x    = (const float*)d_in[0];
    // d_in[1] = degrees (unused by reference)
    const int*   eidx = (const int*)d_in[2];   // JAX demotes int64 -> int32 (x64 disabled)
    const float* W1m  = (const float*)d_in[3];
    const float* b1m  = (const float*)d_in[4];
    const float* W2m  = (const float*)d_in[5];
    const float* b2m  = (const float*)d_in[6];
    const float* W1u  = (const float*)d_in[7];
    const float* b1u  = (const float*)d_in[8];
    const float* W2u  = (const float*)d_in[9];
    const float* b2u  = (const float*)d_in[10];
    float* out = (float*)d_out;

    int N = in_sizes[0] / 128;
    int E = in_sizes[2] / 2;

    float* agg = nullptr;
    cudaGetSymbolAddress((void**)&agg, g_agg);

    const int smemBytes = (TE * 256 + 32 * 128 + TE * 128) * 4 + TE * 3 * 4;
    cudaFuncSetAttribute((const void*)mlp_kernel<true>,
                         cudaFuncAttributeMaxDynamicSharedMemorySize, smemBytes);
    cudaFuncSetAttribute((const void*)mlp_kernel<false>,
                         cudaFuncAttributeMaxDynamicSharedMemorySize, smemBytes);

    int n4 = (N * 128) / 4;
    zero_agg_kernel<<<(n4 + 255) / 256, 256>>>(agg, n4);

    mlp_kernel<true><<<(E + TE - 1) / TE, NTHREADS, smemBytes>>>(
        x, x, eidx, W1m, b1m, W2m, b2m, agg, E, E);

    mlp_kernel<false><<<(N + TE - 1) / TE, NTHREADS, smemBytes>>>(
        x, agg, nullptr, W1u, b1u, W2u, b2u, out, N, 0);
}

// round 3
// speedup vs baseline: 1.0807x; 1.0807x over previous
#include <cuda_runtime.h>
#include <cstdint>

#define NT 256
#define TE 32
#define AST 36   // transposed-A smem stride (16B-aligned, conflict-avoiding)

using u64 = unsigned long long;

// scatter-sum scratch (N_NODES * D_MSG), zeroed every call
__device__ float g_agg[50000 * 128];

__device__ __forceinline__ u64 pk2(float lo, float hi) {
    u64 r;
    asm("mov.b64 %0, {%1, %2};" : "=l"(r) : "f"(lo), "f"(hi));
    return r;
}
__device__ __forceinline__ void upk2(u64 v, float& lo, float& hi) {
    asm("mov.b64 {%0, %1}, %2;" : "=f"(lo), "=f"(hi) : "l"(v));
}
// packed dual-fp32 FMA (FFMA2) — only reachable via PTX on sm_103a
__device__ __forceinline__ u64 fma2(u64 a, u64 b, u64 c) {
    u64 d;
    asm("fma.rn.f32x2 %0, %1, %2, %3;" : "=l"(d) : "l"(a), "l"(b), "l"(c));
    return d;
}

__global__ void zero_agg_kernel(float* agg, int n4) {
    int i = blockIdx.x * blockDim.x + threadIdx.x;
    if (i < n4) ((float4*)agg)[i] = make_float4(0.f, 0.f, 0.f, 0.f);
}

__device__ __forceinline__ void prefetch_slab(const float* gp, int gstride,
                                              float* dstbase, int tid) {
#pragma unroll
    for (int j = 0; j < 4; j++) {
        int e = tid + j * NT;
        int k = e >> 5, c = (e & 31) * 4;
        unsigned dst = (unsigned)__cvta_generic_to_shared(dstbase + k * 128 + c);
        asm volatile("cp.async.cg.shared.global [%0], [%1], 16;"
                     :: "r"(dst), "l"(gp + (size_t)k * gstride + c));
    }
    asm volatile("cp.async.commit_group;");
}

// 32-k slab GEMM micro-kernel: acc[cc*4+rp] accumulates rows (r0+2rp, r0+2rp+1)
// packed in f32x2 halves, cols c0+cc.
__device__ __forceinline__ void slab_mm(const float* __restrict__ ab,
                                        const float* __restrict__ wb,
                                        u64 (&acc)[8]) {
#pragma unroll
    for (int k = 0; k < 32; k++) {
        ulonglong2 a01 = *(const ulonglong2*)(ab + k * AST);
        ulonglong2 a23 = *(const ulonglong2*)(ab + k * AST + 4);
        float2 w = *(const float2*)(wb + k * 128);
        u64 ww0 = pk2(w.x, w.x), ww1 = pk2(w.y, w.y);
        acc[0] = fma2(a01.x, ww0, acc[0]);
        acc[1] = fma2(a01.y, ww0, acc[1]);
        acc[2] = fma2(a23.x, ww0, acc[2]);
        acc[3] = fma2(a23.y, ww0, acc[3]);
        acc[4] = fma2(a01.x, ww1, acc[4]);
        acc[5] = fma2(a01.y, ww1, acc[5]);
        acc[6] = fma2(a23.x, ww1, acc[6]);
        acc[7] = fma2(a23.y, ww1, acc[7]);
    }
}

// Fused 2-layer MLP over 32-row tiles, transposed-A f32x2 micro-kernel,
// cp.async double-buffered weight slabs.
// IS_EDGE:  rows = edges;  A = [x[tgt] | x[src]], result atomic-added to agg[tgt].
// !IS_EDGE: rows = nodes;  A = [x[n]   | agg[n] ], result stored to out[n].
template <bool IS_EDGE>
__global__ __launch_bounds__(NT, 2)
void mlp_kernel(const float* __restrict__ x,
                const float* __restrict__ second,
                const int* __restrict__ eidx,
                const float* __restrict__ W1, const float* __restrict__ b1,
                const float* __restrict__ W2, const float* __restrict__ b2,
                float* __restrict__ out,
                int M, int E) {
    extern __shared__ float smem[];
    float* As_t = smem;                  // [256][AST]
    float* Hs_t = As_t + 256 * AST;      // [128][AST]
    float* Ws   = Hs_t + 128 * AST;      // [2][32][128]
    int* sA = (int*)(Ws + 2 * 32 * 128);
    int* sB = sA + TE;
    int* sV = sB + TE;

    const int tid = threadIdx.x;
    const int rowbase = blockIdx.x * TE;

    if (tid < TE) {
        int r = rowbase + tid;
        int valid = (r < M) ? 1 : 0;
        int na = 0, nb = 0;
        if (valid) {
            if (IS_EDGE) { nb = eidx[r]; na = eidx[E + r]; }  // j=src, i=tgt
            else         { na = r; nb = r; }
        }
        sA[tid] = na; sB[tid] = nb; sV[tid] = valid;
    }
    __syncthreads();

    // kick off first weight slab while gathering A
    prefetch_slab(W1, 512, Ws, tid);

    // gather A transposed: As_t[c][r]; cols [0,128)=x[na], [128,256)=x/agg[nb]
    {
        int r = tid >> 3;
        int cb = (tid & 7) * 32;
        int na = sA[r], nb = sB[r], v = sV[r];
        const float* rowA = x + (size_t)na * 128;
        const float* rowB = (IS_EDGE ? x : second) + (size_t)nb * 128;
#pragma unroll
        for (int j = 0; j < 8; j++) {
            int c = cb + j * 4;
            float4 val = make_float4(0.f, 0.f, 0.f, 0.f);
            if (v) val = (c < 128) ? *(const float4*)(rowA + c)
                                   : *(const float4*)(rowB + c - 128);
            As_t[(c + 0) * AST + r] = val.x;
            As_t[(c + 1) * AST + r] = val.y;
            As_t[(c + 2) * AST + r] = val.z;
            As_t[(c + 3) * AST + r] = val.w;
        }
    }

    const int rg = tid >> 6;        // 4 row-groups of 8 rows
    const int lg = tid & 63;        // 64 col-groups of 2 cols
    const int r0 = rg * 8;
    const int c0 = lg * 2;

    u64 msg[8];
    {
        float m0 = b2[c0], m1 = b2[c0 + 1];
#pragma unroll
        for (int rp = 0; rp < 4; rp++) { msg[rp] = pk2(m0, m0); msg[4 + rp] = pk2(m1, m1); }
    }

    int buf = 0;
    for (int chunk = 0; chunk < 4; chunk++) {
        u64 hc[8];
        {
            float h0 = b1[chunk * 128 + c0], h1 = b1[chunk * 128 + c0 + 1];
#pragma unroll
            for (int rp = 0; rp < 4; rp++) { hc[rp] = pk2(h0, h0); hc[4 + rp] = pk2(h1, h1); }
        }
        for (int sl = 0; sl < 12; sl++) {
            // prefetch next slab (flat schedule: 8 W1 slabs then 4 W2 slabs per chunk)
            int ns = sl + 1, nchunk = chunk;
            if (ns == 12) { ns = 0; nchunk++; }
            if (nchunk < 4) {
                const float* np;
                int nstr;
                if (ns < 8) { np = W1 + ns * 32 * 512 + nchunk * 128; nstr = 512; }
                else        { np = W2 + (size_t)(nchunk * 128 + (ns - 8) * 32) * 128; nstr = 128; }
                prefetch_slab(np, nstr, Ws + (buf ^ 1) * 4096, tid);
                asm volatile("cp.async.wait_group 1;");
            } else {
                asm volatile("cp.async.wait_group 0;");
            }
            __syncthreads();

            const float* wb = Ws + buf * 4096 + c0;
            if (sl < 8) {
                slab_mm(As_t + sl * 32 * AST + r0, wb, hc);
                if (sl == 7) {
                    // relu -> Hs_t (transposed), pairs stay packed
#pragma unroll
                    for (int cc = 0; cc < 2; cc++)
#pragma unroll
                        for (int rp = 0; rp < 4; rp++) {
                            float f0, f1;
                            upk2(hc[cc * 4 + rp], f0, f1);
                            f0 = fmaxf(f0, 0.f);
                            f1 = fmaxf(f1, 0.f);
                            *(u64*)&Hs_t[(c0 + cc) * AST + r0 + rp * 2] = pk2(f0, f1);
                        }
                }
            } else {
                slab_mm(Hs_t + (sl - 8) * 32 * AST + r0, wb, msg);
            }
            __syncthreads();
            buf ^= 1;
        }
    }

    // emit: rows r0..r0+7, cols c0..c0+1
#pragma unroll
    for (int rp = 0; rp < 4; rp++) {
        float a0, a1, b0v, b1v;
        upk2(msg[rp], a0, a1);        // col c0:   (row even, row odd)
        upk2(msg[4 + rp], b0v, b1v);  // col c0+1: (row even, row odd)
#pragma unroll
        for (int q = 0; q < 2; q++) {
            int r = r0 + rp * 2 + q;
            if (!sV[r]) continue;
            float e0 = q ? a1 : a0;
            float e1 = q ? b1v : b0v;
            if (IS_EDGE) {
                float* dst = out + (size_t)sA[r] * 128 + c0;
                atomicAdd(dst + 0, e0);
                atomicAdd(dst + 1, e1);
            } else {
                float* dst = out + (size_t)(rowbase + r) * 128 + c0;
                dst[0] = e0;
                dst[1] = e1;
            }
        }
    }
}

extern "C" void kernel_launch(void* const* d_in, const int* in_sizes, int n_in,
                              void* d_out, int out_size) {
    const float* x    = (const float*)d_in[0];
    // d_in[1] = degrees (unused by reference)
    const int*   eidx = (const int*)d_in[2];   // JAX demotes int64 -> int32
    const float* W1m  = (const float*)d_in[3];
    const float* b1m  = (const float*)d_in[4];
    const float* W2m  = (const float*)d_in[5];
    const float* b2m  = (const float*)d_in[6];
    const float* W1u  = (const float*)d_in[7];
    const float* b1u  = (const float*)d_in[8];
    const float* W2u  = (const float*)d_in[9];
    const float* b2u  = (const float*)d_in[10];
    float* out = (float*)d_out;

    int N = in_sizes[0] / 128;
    int E = in_sizes[2] / 2;

    float* agg = nullptr;
    cudaGetSymbolAddress((void**)&agg, g_agg);

    const int smemBytes = (256 * AST + 128 * AST + 2 * 32 * 128) * 4 + TE * 3 * 4;
    cudaFuncSetAttribute((const void*)mlp_kernel<true>,
                         cudaFuncAttributeMaxDynamicSharedMemorySize, smemBytes);
    cudaFuncSetAttribute((const void*)mlp_kernel<false>,
                         cudaFuncAttributeMaxDynamicSharedMemorySize, smemBytes);

    int n4 = (N * 128) / 4;
    zero_agg_kernel<<<(n4 + 255) / 256, 256>>>(agg, n4);

    mlp_kernel<true><<<(E + TE - 1) / TE, NT, smemBytes>>>(
        x, x, eidx, W1m, b1m, W2m, b2m, agg, E, E);

    mlp_kernel<false><<<(N + TE - 1) / TE, NT, smemBytes>>>(
        x, agg, nullptr, W1u, b1u, W2u, b2u, out, N, 0);
}

// round 5
// speedup vs baseline: 2.4340x; 2.2522x over previous
#include <cuda_runtime.h>
#include <cuda_bf16.h>
#include <cstdint>

#define NT 256
// smem byte offsets
#define SM_AHI 0
#define SM_ALO 33792
#define SM_WB  67584
#define WB_STRIDE 54272
#define WB_W1HI 0
#define WB_W1LO 16896
#define WB_W2HI 33792
#define WB_W2LO 44032
#define SM_HHI 176128
#define SM_HLO 181248
#define SM_TOTAL 186368
// row strides (bytes): A/W1 = 264 bf16 = 528B ; H/W2 = 40 bf16 = 80B

__device__ float g_agg[50000 * 128];
__device__ __align__(16) __nv_bfloat16 g_w1m_hi[512 * 264];
__device__ __align__(16) __nv_bfloat16 g_w1m_lo[512 * 264];
__device__ __align__(16) __nv_bfloat16 g_w2m_hi[16 * 128 * 40];
__device__ __align__(16) __nv_bfloat16 g_w2m_lo[16 * 128 * 40];
__device__ __align__(16) __nv_bfloat16 g_w1u_hi[512 * 264];
__device__ __align__(16) __nv_bfloat16 g_w1u_lo[512 * 264];
__device__ __align__(16) __nv_bfloat16 g_w2u_hi[16 * 128 * 40];
__device__ __align__(16) __nv_bfloat16 g_w2u_lo[16 * 128 * 40];

__device__ __forceinline__ uint32_t smem_u32(const void* p) {
    uint32_t a;
    asm("{ .reg .u64 t; cvta.to.shared.u64 t, %1; cvt.u32.u64 %0, t; }" : "=r"(a) : "l"(p));
    return a;
}
__device__ __forceinline__ void ldm4(uint32_t addr, uint32_t& r0, uint32_t& r1,
                                     uint32_t& r2, uint32_t& r3) {
    asm volatile("ldmatrix.sync.aligned.m8n8.x4.shared.b16 {%0,%1,%2,%3}, [%4];"
                 : "=r"(r0), "=r"(r1), "=r"(r2), "=r"(r3) : "r"(addr));
}
__device__ __forceinline__ void mma_bf(float* c, uint32_t a0, uint32_t a1,
                                       uint32_t a2, uint32_t a3,
                                       uint32_t b0, uint32_t b1) {
    asm volatile(
        "mma.sync.aligned.m16n8k16.row.col.f32.bf16.bf16.f32 "
        "{%0,%1,%2,%3}, {%4,%5,%6,%7}, {%8,%9}, {%0,%1,%2,%3};"
        : "+f"(c[0]), "+f"(c[1]), "+f"(c[2]), "+f"(c[3])
        : "r"(a0), "r"(a1), "r"(a2), "r"(a3), "r"(b0), "r"(b1));
}
__device__ __forceinline__ void cp16(uint32_t dst, const void* src) {
    asm volatile("cp.async.cg.shared.global [%0], [%1], 16;" :: "r"(dst), "l"(src));
}
__device__ __forceinline__ uint32_t packbf(float a, float b, float& la, float& lb) {
    __nv_bfloat16 ha = __float2bfloat16_rn(a), hb = __float2bfloat16_rn(b);
    la = a - __bfloat162float(ha);
    lb = b - __bfloat162float(hb);
    uint16_t ua = *(uint16_t*)&ha, ub = *(uint16_t*)&hb;
    return (uint32_t)ua | ((uint32_t)ub << 16);
}
__device__ __forceinline__ uint32_t packbf_only(float a, float b) {
    __nv_bfloat16 ha = __float2bfloat16_rn(a), hb = __float2bfloat16_rn(b);
    uint16_t ua = *(uint16_t*)&ha, ub = *(uint16_t*)&hb;
    return (uint32_t)ua | ((uint32_t)ub << 16);
}

__global__ void zero_agg_kernel(float* agg, int n4) {
    int i = blockIdx.x * blockDim.x + threadIdx.x;
    if (i < n4) ((float4*)agg)[i] = make_float4(0.f, 0.f, 0.f, 0.f);
}
// W1 [256k x 512n] -> img [512n][264k] hi/lo bf16 (transposed, padded)
__global__ void prep_w1(const float* __restrict__ W, __nv_bfloat16* hi, __nv_bfloat16* lo) {
    int idx = blockIdx.x * blockDim.x + threadIdx.x;  // 131072
    int k = idx >> 9, n = idx & 511;
    float v = W[idx];
    __nv_bfloat16 h = __float2bfloat16_rn(v);
    hi[n * 264 + k] = h;
    lo[n * 264 + k] = __float2bfloat16_rn(v - __bfloat162float(h));
}
// W2 [512k x 128n] -> img [16 chunk][128n][40k] hi/lo
__global__ void prep_w2(const float* __restrict__ W, __nv_bfloat16* hi, __nv_bfloat16* lo) {
    int idx = blockIdx.x * blockDim.x + threadIdx.x;  // 65536
    int k = idx >> 7, n = idx & 127;
    float v = W[idx];
    __nv_bfloat16 h = __float2bfloat16_rn(v);
    int pos = (k >> 5) * 5120 + n * 40 + (k & 31);
    hi[pos] = h;
    lo[pos] = __float2bfloat16_rn(v - __bfloat162float(h));
}

__device__ __forceinline__ void prefetch_slab(uint32_t wb, int c,
        const __nv_bfloat16* w1h, const __nv_bfloat16* w1l,
        const __nv_bfloat16* w2h, const __nv_bfloat16* w2l, int tid) {
    const char* s1h = ((const char*)w1h) + c * 16896;
    const char* s1l = ((const char*)w1l) + c * 16896;
    const char* s2h = ((const char*)w2h) + c * 10240;
    const char* s2l = ((const char*)w2l) + c * 10240;
#pragma unroll
    for (int j = 0; j < 5; ++j) {
        int idx = tid + j * NT;
        if (idx < 1056) {
            cp16(wb + WB_W1HI + idx * 16, s1h + idx * 16);
            cp16(wb + WB_W1LO + idx * 16, s1l + idx * 16);
        }
    }
#pragma unroll
    for (int j = 0; j < 3; ++j) {
        int idx = tid + j * NT;
        if (idx < 640) {
            cp16(wb + WB_W2HI + idx * 16, s2h + idx * 16);
            cp16(wb + WB_W2LO + idx * 16, s2l + idx * 16);
        }
    }
    asm volatile("cp.async.commit_group;");
}

// Fused 2-layer MLP, 64 rows/CTA, bf16 hi/lo 3-term mma.sync.
template <bool IS_EDGE>
__global__ __launch_bounds__(NT, 1)
void mlp_mma(const float* __restrict__ x, const float* __restrict__ second,
             const int* __restrict__ eidx,
             const __nv_bfloat16* __restrict__ w1h, const __nv_bfloat16* __restrict__ w1l,
             const __nv_bfloat16* __restrict__ w2h, const __nv_bfloat16* __restrict__ w2l,
             const float* __restrict__ b1, const float* __restrict__ b2,
             float* __restrict__ out, int M, int E) {
    extern __shared__ __align__(16) unsigned char smem[];
    const uint32_t sb = smem_u32(smem);
    const int tid = threadIdx.x;
    const int lane = tid & 31;
    const int wid = tid >> 5;
    const int wm = wid & 3, wn = wid >> 2;
    const int rowbase = blockIdx.x * 64;

    prefetch_slab(sb + SM_WB, 0, w1h, w1l, w2h, w2l, tid);

    // ---- gather A = [feat0(128) | feat1(128)] -> hi/lo bf16 smem (padded rows) ----
    {
        int r = tid >> 2, q = tid & 3;
        int row = rowbase + r;
        const float* src;
        if (IS_EDGE) {
            int e = (row < E) ? row : 0;
            int node = (q < 2) ? eidx[E + e] : eidx[e];   // i for cols<128, j after
            src = x + (size_t)node * 128 + (q & 1) * 64;
        } else {
            int n = (row < M) ? row : 0;
            src = ((q < 2) ? x : second) + (size_t)n * 128 + (q & 1) * 64;
        }
        uint32_t abase = (uint32_t)(r * 528 + q * 128);
#pragma unroll
        for (int jj = 0; jj < 16; ++jj) {
            float4 v = *(const float4*)(src + jj * 4);
            float lx, ly, lz, lw;
            uint32_t h0 = packbf(v.x, v.y, lx, ly);
            uint32_t h1 = packbf(v.z, v.w, lz, lw);
            uint32_t l0 = packbf_only(lx, ly);
            uint32_t l1 = packbf_only(lz, lw);
            asm volatile("st.shared.v2.b32 [%0], {%1,%2};"
                         :: "r"(sb + SM_AHI + abase + jj * 8), "r"(h0), "r"(h1) : "memory");
            asm volatile("st.shared.v2.b32 [%0], {%1,%2};"
                         :: "r"(sb + SM_ALO + abase + jj * 8), "r"(l0), "r"(l1) : "memory");
        }
    }

    // ldmatrix lane-address offsets (byte offsets within arrays)
    const uint32_t aOff = (uint32_t)((wm * 16 + (lane & 7) + ((lane >> 3) & 1) * 8) * 528 +
                                     ((lane >> 4) & 1) * 16);
    const uint32_t bOff = (uint32_t)((wn * 16 + (lane & 7) + ((lane >> 4) & 1) * 8) * 528 +
                                     ((lane >> 3) & 1) * 16);
    const uint32_t hOff = (uint32_t)((wm * 16 + (lane & 7) + ((lane >> 3) & 1) * 8) * 80 +
                                     ((lane >> 4) & 1) * 16);
    uint32_t w2Off[4];
#pragma unroll
    for (int p = 0; p < 4; ++p)
        w2Off[p] = (uint32_t)((wn * 64 + p * 16 + (lane & 7) + ((lane >> 4) & 1) * 8) * 80 +
                              ((lane >> 3) & 1) * 16);

    float acc2[32];
#pragma unroll
    for (int i = 0; i < 32; ++i) acc2[i] = 0.f;

    const int r_lo = wm * 16 + (lane >> 2);
    const int cc = (lane & 3) * 2;

    int buf = 0;
    for (int c = 0; c < 16; ++c) {
        asm volatile("cp.async.wait_group 0;");
        __syncthreads();
        const uint32_t wb = sb + SM_WB + (uint32_t)buf * WB_STRIDE;
        if (c + 1 < 16)
            prefetch_slab(sb + SM_WB + (uint32_t)(buf ^ 1) * WB_STRIDE, c + 1,
                          w1h, w1l, w2h, w2l, tid);

        // ---- GEMM1: acc1[64x32chunk] over K=256 ----
        float acc1[8];
#pragma unroll
        for (int i = 0; i < 8; ++i) acc1[i] = 0.f;
#pragma unroll
        for (int s = 0; s < 16; ++s) {
            uint32_t ah0, ah1, ah2, ah3, al0, al1, al2, al3;
            uint32_t bh0, bh1, bh2, bh3, bl0, bl1, bl2, bl3;
            ldm4(sb + SM_AHI + aOff + s * 32, ah0, ah1, ah2, ah3);
            ldm4(sb + SM_ALO + aOff + s * 32, al0, al1, al2, al3);
            ldm4(wb + WB_W1HI + bOff + s * 32, bh0, bh1, bh2, bh3);
            ldm4(wb + WB_W1LO + bOff + s * 32, bl0, bl1, bl2, bl3);
            mma_bf(acc1 + 0, ah0, ah1, ah2, ah3, bh0, bh1);
            mma_bf(acc1 + 4, ah0, ah1, ah2, ah3, bh2, bh3);
            mma_bf(acc1 + 0, ah0, ah1, ah2, ah3, bl0, bl1);
            mma_bf(acc1 + 4, ah0, ah1, ah2, ah3, bl2, bl3);
            mma_bf(acc1 + 0, al0, al1, al2, al3, bh0, bh1);
            mma_bf(acc1 + 4, al0, al1, al2, al3, bh2, bh3);
        }

        // ---- epilogue: relu(acc1 + b1), split hi/lo -> H smem ----
#pragma unroll
        for (int t = 0; t < 2; ++t) {
            int gcol = c * 32 + wn * 16 + t * 8 + cc;
            float ba = __ldg(b1 + gcol), bb = __ldg(b1 + gcol + 1);
            float v00 = fmaxf(acc1[t * 4 + 0] + ba, 0.f);
            float v01 = fmaxf(acc1[t * 4 + 1] + bb, 0.f);
            float v10 = fmaxf(acc1[t * 4 + 2] + ba, 0.f);
            float v11 = fmaxf(acc1[t * 4 + 3] + bb, 0.f);
            int hcol = wn * 16 + t * 8 + cc;
            float l00, l01, l10, l11;
            uint32_t h0 = packbf(v00, v01, l00, l01);
            uint32_t h1 = packbf(v10, v11, l10, l11);
            uint32_t lo0 = packbf_only(l00, l01);
            uint32_t lo1 = packbf_only(l10, l11);
            uint32_t a0 = sb + SM_HHI + r_lo * 80 + hcol * 2;
            uint32_t a1 = sb + SM_HHI + (r_lo + 8) * 80 + hcol * 2;
            asm volatile("st.shared.b32 [%0], %1;" :: "r"(a0), "r"(h0) : "memory");
            asm volatile("st.shared.b32 [%0], %1;" :: "r"(a1), "r"(h1) : "memory");
            asm volatile("st.shared.b32 [%0], %1;" :: "r"(a0 + (SM_HLO - SM_HHI)), "r"(lo0) : "memory");
            asm volatile("st.shared.b32 [%0], %1;" :: "r"(a1 + (SM_HLO - SM_HHI)), "r"(lo1) : "memory");
        }
        __syncthreads();

        // ---- GEMM2: acc2 += H[64x32] @ W2chunk[32x128] ----
#pragma unroll
        for (int s = 0; s < 2; ++s) {
            uint32_t hh0, hh1, hh2, hh3, hl0, hl1, hl2, hl3;
            ldm4(sb + SM_HHI + hOff + s * 32, hh0, hh1, hh2, hh3);
            ldm4(sb + SM_HLO + hOff + s * 32, hl0, hl1, hl2, hl3);
#pragma unroll
            for (int p = 0; p < 4; ++p) {
                uint32_t bh0, bh1, bh2, bh3, bl0, bl1, bl2, bl3;
                ldm4(wb + WB_W2HI + w2Off[p] + s * 32, bh0, bh1, bh2, bh3);
                ldm4(wb + WB_W2LO + w2Off[p] + s * 32, bl0, bl1, bl2, bl3);
                float* acp = acc2 + p * 8;
                mma_bf(acp + 0, hh0, hh1, hh2, hh3, bh0, bh1);
                mma_bf(acp + 4, hh0, hh1, hh2, hh3, bh2, bh3);
                mma_bf(acp + 0, hh0, hh1, hh2, hh3, bl0, bl1);
                mma_bf(acp + 4, hh0, hh1, hh2, hh3, bl2, bl3);
                mma_bf(acp + 0, hl0, hl1, hl2, hl3, bh0, bh1);
                mma_bf(acp + 4, hl0, hl1, hl2, hl3, bh2, bh3);
            }
        }
        buf ^= 1;
    }

    // ---- final epilogue: out = acc2 + b2 ----
    {
        int e0 = rowbase + r_lo;
        int e1 = e0 + 8;
        int tgt0 = 0, tgt1 = 0;
        if (IS_EDGE) {
            tgt0 = (e0 < E) ? eidx[E + e0] : 0;
            tgt1 = (e1 < E) ? eidx[E + e1] : 0;
        }
#pragma unroll
        for (int p = 0; p < 4; ++p) {
#pragma unroll
            for (int t = 0; t < 2; ++t) {
                int col = wn * 64 + p * 16 + t * 8 + cc;
                float ba = __ldg(b2 + col), bb = __ldg(b2 + col + 1);
                float v00 = acc2[p * 8 + t * 4 + 0] + ba;
                float v01 = acc2[p * 8 + t * 4 + 1] + bb;
                float v10 = acc2[p * 8 + t * 4 + 2] + ba;
                float v11 = acc2[p * 8 + t * 4 + 3] + bb;
                if (IS_EDGE) {
                    if (e0 < E) {
                        atomicAdd(out + (size_t)tgt0 * 128 + col, v00);
                        atomicAdd(out + (size_t)tgt0 * 128 + col + 1, v01);
                    }
                    if (e1 < E) {
                        atomicAdd(out + (size_t)tgt1 * 128 + col, v10);
                        atomicAdd(out + (size_t)tgt1 * 128 + col + 1, v11);
                    }
                } else {
                    if (e0 < M) *(float2*)(out + (size_t)e0 * 128 + col) = make_float2(v00, v01);
                    if (e1 < M) *(float2*)(out + (size_t)e1 * 128 + col) = make_float2(v10, v11);
                }
            }
        }
    }
}

extern "C" void kernel_launch(void* const* d_in, const int* in_sizes, int n_in,
                              void* d_out, int out_size) {
    const float* x   = (const float*)d_in[0];
    const int* eidx  = (const int*)d_in[2];   // JAX demotes int64 -> int32
    const float* W1m = (const float*)d_in[3];
    const float* b1m = (const float*)d_in[4];
    const float* W2m = (const float*)d_in[5];
    const float* b2m = (const float*)d_in[6];
    const float* W1u = (const float*)d_in[7];
    const float* b1u = (const float*)d_in[8];
    const float* W2u = (const float*)d_in[9];
    const float* b2u = (const float*)d_in[10];
    float* out = (float*)d_out;

    int N = in_sizes[0] / 128;
    int E = in_sizes[2] / 2;

    float* agg; cudaGetSymbolAddress((void**)&agg, g_agg);
    __nv_bfloat16 *w1mh, *w1ml, *w2mh, *w2ml, *w1uh, *w1ul, *w2uh, *w2ul;
    cudaGetSymbolAddress((void**)&w1mh, g_w1m_hi);
    cudaGetSymbolAddress((void**)&w1ml, g_w1m_lo);
    cudaGetSymbolAddress((void**)&w2mh, g_w2m_hi);
    cudaGetSymbolAddress((void**)&w2ml, g_w2m_lo);
    cudaGetSymbolAddress((void**)&w1uh, g_w1u_hi);
    cudaGetSymbolAddress((void**)&w1ul, g_w1u_lo);
    cudaGetSymbolAddress((void**)&w2uh, g_w2u_hi);
    cudaGetSymbolAddress((void**)&w2ul, g_w2u_lo);

    cudaFuncSetAttribute((const void*)mlp_mma<true>,
                         cudaFuncAttributeMaxDynamicSharedMemorySize, SM_TOTAL);
    cudaFuncSetAttribute((const void*)mlp_mma<false>,
                         cudaFuncAttributeMaxDynamicSharedMemorySize, SM_TOTAL);

    int n4 = (N * 128) / 4;
    zero_agg_kernel<<<(n4 + 255) / 256, 256>>>(agg, n4);
    prep_w1<<<512, 256>>>(W1m, w1mh, w1ml);
    prep_w2<<<256, 256>>>(W2m, w2mh, w2ml);
    prep_w1<<<512, 256>>>(W1u, w1uh, w1ul);
    prep_w2<<<256, 256>>>(W2u, w2uh, w2ul);

    mlp_mma<true><<<(E + 63) / 64, NT, SM_TOTAL>>>(
        x, x, eidx, w1mh, w1ml, w2mh, w2ml, b1m, b2m, agg, E, E);

    mlp_mma<false><<<(N + 63) / 64, NT, SM_TOTAL>>>(
        x, agg, nullptr, w1uh, w1ul, w2uh, w2ul, b1u, b2u, out, N, 0);
}

// round 6
// speedup vs baseline: 2.9112x; 1.1960x over previous
#include <cuda_runtime.h>
#include <cuda_bf16.h>
#include <cstdint>

#define NT 256
#define ROWS 128
// smem byte offsets
#define SM_AHI   0
#define SM_ALO   67584
#define SM_W1HI  135168
#define SM_W1LO  152064
#define SM_W2HI  168960
#define SM_W2LO  179200
#define SM_HHI   189440
#define SM_HLO   199680
#define SM_TOTAL 209920
// row strides (bytes): A/W1 = 264 bf16 = 528B ; H/W2 = 40 bf16 = 80B

__device__ float g_agg[50000 * 128];
__device__ __align__(16) __nv_bfloat16 g_w1m_hi[512 * 264];
__device__ __align__(16) __nv_bfloat16 g_w1m_lo[512 * 264];
__device__ __align__(16) __nv_bfloat16 g_w2m_hi[16 * 128 * 40];
__device__ __align__(16) __nv_bfloat16 g_w2m_lo[16 * 128 * 40];
__device__ __align__(16) __nv_bfloat16 g_w1u_hi[512 * 264];
__device__ __align__(16) __nv_bfloat16 g_w1u_lo[512 * 264];
__device__ __align__(16) __nv_bfloat16 g_w2u_hi[16 * 128 * 40];
__device__ __align__(16) __nv_bfloat16 g_w2u_lo[16 * 128 * 40];

__device__ __forceinline__ uint32_t smem_u32(const void* p) {
    uint32_t a;
    asm("{ .reg .u64 t; cvta.to.shared.u64 t, %1; cvt.u32.u64 %0, t; }" : "=r"(a) : "l"(p));
    return a;
}
__device__ __forceinline__ void ldm4(uint32_t addr, uint32_t* r) {
    asm volatile("ldmatrix.sync.aligned.m8n8.x4.shared.b16 {%0,%1,%2,%3}, [%4];"
                 : "=r"(r[0]), "=r"(r[1]), "=r"(r[2]), "=r"(r[3]) : "r"(addr));
}
__device__ __forceinline__ void mma_bf(float* c, const uint32_t* a,
                                       uint32_t b0, uint32_t b1) {
    asm volatile(
        "mma.sync.aligned.m16n8k16.row.col.f32.bf16.bf16.f32 "
        "{%0,%1,%2,%3}, {%4,%5,%6,%7}, {%8,%9}, {%0,%1,%2,%3};"
        : "+f"(c[0]), "+f"(c[1]), "+f"(c[2]), "+f"(c[3])
        : "r"(a[0]), "r"(a[1]), "r"(a[2]), "r"(a[3]), "r"(b0), "r"(b1));
}
__device__ __forceinline__ void cp16(uint32_t dst, const void* src) {
    asm volatile("cp.async.cg.shared.global [%0], [%1], 16;" :: "r"(dst), "l"(src));
}
__device__ __forceinline__ uint32_t packbf(float a, float b, float& la, float& lb) {
    __nv_bfloat16 ha = __float2bfloat16_rn(a), hb = __float2bfloat16_rn(b);
    la = a - __bfloat162float(ha);
    lb = b - __bfloat162float(hb);
    uint16_t ua = *(uint16_t*)&ha, ub = *(uint16_t*)&hb;
    return (uint32_t)ua | ((uint32_t)ub << 16);
}
__device__ __forceinline__ uint32_t packbf_only(float a, float b) {
    __nv_bfloat16 ha = __float2bfloat16_rn(a), hb = __float2bfloat16_rn(b);
    uint16_t ua = *(uint16_t*)&ha, ub = *(uint16_t*)&hb;
    return (uint32_t)ua | ((uint32_t)ub << 16);
}

__global__ void zero_agg_kernel(float* agg, int n4) {
    int i = blockIdx.x * blockDim.x + threadIdx.x;
    if (i < n4) ((float4*)agg)[i] = make_float4(0.f, 0.f, 0.f, 0.f);
}
// W1 [256k x 512n] -> img [512n][264k] hi/lo bf16 (transposed, padded)
__global__ void prep_w1(const float* __restrict__ W, __nv_bfloat16* hi, __nv_bfloat16* lo) {
    int idx = blockIdx.x * blockDim.x + threadIdx.x;  // 131072
    int k = idx >> 9, n = idx & 511;
    float v = W[idx];
    __nv_bfloat16 h = __float2bfloat16_rn(v);
    hi[n * 264 + k] = h;
    lo[n * 264 + k] = __float2bfloat16_rn(v - __bfloat162float(h));
}
// W2 [512k x 128n] -> img [16 chunk][128n][40k] hi/lo
__global__ void prep_w2(const float* __restrict__ W, __nv_bfloat16* hi, __nv_bfloat16* lo) {
    int idx = blockIdx.x * blockDim.x + threadIdx.x;  // 65536
    int k = idx >> 7, n = idx & 127;
    float v = W[idx];
    __nv_bfloat16 h = __float2bfloat16_rn(v);
    int pos = (k >> 5) * 5120 + n * 40 + (k & 31);
    hi[pos] = h;
    lo[pos] = __float2bfloat16_rn(v - __bfloat162float(h));
}

__device__ __forceinline__ void prefetch_w1(uint32_t sb, int c,
        const __nv_bfloat16* w1h, const __nv_bfloat16* w1l, int tid) {
    const char* s1h = ((const char*)w1h) + c * 16896;
    const char* s1l = ((const char*)w1l) + c * 16896;
#pragma unroll
    for (int j = 0; j < 5; ++j) {
        int idx = tid + j * NT;
        if (idx < 1056) {
            cp16(sb + SM_W1HI + idx * 16, s1h + idx * 16);
            cp16(sb + SM_W1LO + idx * 16, s1l + idx * 16);
        }
    }
    asm volatile("cp.async.commit_group;");
}
__device__ __forceinline__ void prefetch_w2(uint32_t sb, int c,
        const __nv_bfloat16* w2h, const __nv_bfloat16* w2l, int tid) {
    const char* s2h = ((const char*)w2h) + c * 10240;
    const char* s2l = ((const char*)w2l) + c * 10240;
#pragma unroll
    for (int j = 0; j < 3; ++j) {
        int idx = tid + j * NT;
        if (idx < 640) {
            cp16(sb + SM_W2HI + idx * 16, s2h + idx * 16);
            cp16(sb + SM_W2LO + idx * 16, s2l + idx * 16);
        }
    }
    asm volatile("cp.async.commit_group;");
}

// Fused 2-layer MLP, 128 rows/CTA, bf16 hi/lo 3-term mma.sync, m32 warp tiles,
// split-slab cp.async pipeline (W1 prefetched during GEMM2, W2 during GEMM1).
template <bool IS_EDGE>
__global__ __launch_bounds__(NT, 1)
void mlp_mma(const float* __restrict__ x, const float* __restrict__ second,
             const int* __restrict__ eidx,
             const __nv_bfloat16* __restrict__ w1h, const __nv_bfloat16* __restrict__ w1l,
             const __nv_bfloat16* __restrict__ w2h, const __nv_bfloat16* __restrict__ w2l,
             const float* __restrict__ b1, const float* __restrict__ b2,
             float* __restrict__ out, int M, int E) {
    extern __shared__ __align__(16) unsigned char smem[];
    const uint32_t sb = smem_u32(smem);
    const int tid = threadIdx.x;
    const int lane = tid & 31;
    const int wid = tid >> 5;
    const int wm = wid & 3, wn = wid >> 2;   // 4 m-warps x 2 n-warps
    const int rowbase = blockIdx.x * ROWS;

    // chunk-0 weights in flight ASAP (groups: w1_0, w2_0)
    prefetch_w1(sb, 0, w1h, w1l, tid);
    prefetch_w2(sb, 0, w2h, w2l, tid);

    // ---- gather A = [feat_i(128) | feat_j(128)] -> hi/lo bf16 smem ----
    {
        int r = tid >> 1, half = tid & 1;
        int row = rowbase + r;
        const float* src;
        if (IS_EDGE) {
            int e = (row < E) ? row : 0;
            int node = half ? eidx[e] : eidx[E + e];   // half0 = i, half1 = j
            src = x + (size_t)node * 128;
        } else {
            int rr = (row < M) ? row : 0;
            src = (half ? second : x) + (size_t)rr * 128;
        }
        uint32_t abase = sb + SM_AHI + (uint32_t)(r * 528 + half * 256);
#pragma unroll
        for (int jj = 0; jj < 32; ++jj) {
            float4 v = *(const float4*)(src + jj * 4);
            float lx, ly, lz, lw;
            uint32_t h0 = packbf(v.x, v.y, lx, ly);
            uint32_t h1 = packbf(v.z, v.w, lz, lw);
            uint32_t l0 = packbf_only(lx, ly);
            uint32_t l1 = packbf_only(lz, lw);
            asm volatile("st.shared.v2.b32 [%0], {%1,%2};"
                         :: "r"(abase + jj * 8), "r"(h0), "r"(h1) : "memory");
            asm volatile("st.shared.v2.b32 [%0], {%1,%2};"
                         :: "r"(abase + (SM_ALO - SM_AHI) + jj * 8), "r"(l0), "r"(l1) : "memory");
        }
    }

    // ldmatrix base addresses
    const uint32_t aRow = (uint32_t)(wm * 32 + (lane & 15));
    const uint32_t aB0 = sb + SM_AHI + aRow * 528 + (((uint32_t)lane >> 4) & 1) * 16;
    const uint32_t aB1 = aB0 + 16 * 528;
    const uint32_t bB  = sb + SM_W1HI +
        (uint32_t)((wn * 16 + (lane & 7) + ((lane >> 4) & 1) * 8) * 528 +
                   ((lane >> 3) & 1) * 16);
    const uint32_t hB0 = sb + SM_HHI + aRow * 80 + (((uint32_t)lane >> 4) & 1) * 16;
    const uint32_t hB1 = hB0 + 16 * 80;
    uint32_t w2B[4];
#pragma unroll
    for (int p = 0; p < 4; ++p)
        w2B[p] = sb + SM_W2HI +
            (uint32_t)((wn * 64 + p * 16 + (lane & 7) + ((lane >> 4) & 1) * 8) * 80 +
                       ((lane >> 3) & 1) * 16);

    float acc2[64];
#pragma unroll
    for (int i = 0; i < 64; ++i) acc2[i] = 0.f;

    const int rsub = lane >> 2;        // 0..7
    const int cc = (lane & 3) * 2;

    for (int c = 0; c < 16; ++c) {
        asm volatile("cp.async.wait_group 1;");   // W1(c) ready
        __syncthreads();

        // ---- GEMM1: acc1[128 x 32chunk], K=256 ----
        float acc1[16];
#pragma unroll
        for (int i = 0; i < 16; ++i) acc1[i] = 0.f;
#pragma unroll
        for (int s = 0; s < 16; ++s) {
            uint32_t ah0[4], ah1[4], al0[4], al1[4], bh[4], bl[4];
            ldm4(aB0 + s * 32, ah0);
            ldm4(aB1 + s * 32, ah1);
            ldm4(aB0 + (SM_ALO - SM_AHI) + s * 32, al0);
            ldm4(aB1 + (SM_ALO - SM_AHI) + s * 32, al1);
            ldm4(bB + s * 32, bh);
            ldm4(bB + (SM_W1LO - SM_W1HI) + s * 32, bl);
            mma_bf(acc1 + 0,  ah0, bh[0], bh[1]);
            mma_bf(acc1 + 4,  ah0, bh[2], bh[3]);
            mma_bf(acc1 + 0,  ah0, bl[0], bl[1]);
            mma_bf(acc1 + 4,  ah0, bl[2], bl[3]);
            mma_bf(acc1 + 0,  al0, bh[0], bh[1]);
            mma_bf(acc1 + 4,  al0, bh[2], bh[3]);
            mma_bf(acc1 + 8,  ah1, bh[0], bh[1]);
            mma_bf(acc1 + 12, ah1, bh[2], bh[3]);
            mma_bf(acc1 + 8,  ah1, bl[0], bl[1]);
            mma_bf(acc1 + 12, ah1, bl[2], bl[3]);
            mma_bf(acc1 + 8,  al1, bh[0], bh[1]);
            mma_bf(acc1 + 12, al1, bh[2], bh[3]);
        }

        // ---- epilogue: relu(acc1 + b1) -> hi/lo H smem ----
#pragma unroll
        for (int mh = 0; mh < 2; ++mh) {
#pragma unroll
            for (int nh = 0; nh < 2; ++nh) {
                const float* ac = acc1 + mh * 8 + nh * 4;
                int gcol = c * 32 + wn * 16 + nh * 8 + cc;
                float ba = __ldg(b1 + gcol), bb = __ldg(b1 + gcol + 1);
                float v00 = fmaxf(ac[0] + ba, 0.f);
                float v01 = fmaxf(ac[1] + bb, 0.f);
                float v10 = fmaxf(ac[2] + ba, 0.f);
                float v11 = fmaxf(ac[3] + bb, 0.f);
                float l00, l01, l10, l11;
                uint32_t h0 = packbf(v00, v01, l00, l01);
                uint32_t h1 = packbf(v10, v11, l10, l11);
                uint32_t lo0 = packbf_only(l00, l01);
                uint32_t lo1 = packbf_only(l10, l11);
                int hcol = wn * 16 + nh * 8 + cc;
                int r0 = wm * 32 + mh * 16 + rsub;
                uint32_t a0 = sb + SM_HHI + (uint32_t)(r0 * 80 + hcol * 2);
                uint32_t a1 = a0 + 8 * 80;
                asm volatile("st.shared.b32 [%0], %1;" :: "r"(a0), "r"(h0) : "memory");
                asm volatile("st.shared.b32 [%0], %1;" :: "r"(a1), "r"(h1) : "memory");
                asm volatile("st.shared.b32 [%0], %1;" :: "r"(a0 + (SM_HLO - SM_HHI)), "r"(lo0) : "memory");
                asm volatile("st.shared.b32 [%0], %1;" :: "r"(a1 + (SM_HLO - SM_HHI)), "r"(lo1) : "memory");
            }
        }
        __syncthreads();                         // H visible; W1 slab free

        if (c + 1 < 16) {
            prefetch_w1(sb, c + 1, w1h, w1l, tid);
            asm volatile("cp.async.wait_group 1;");   // W2(c) ready
        } else {
            asm volatile("cp.async.wait_group 0;");
        }
        __syncthreads();

        // ---- GEMM2: acc2 += H[128x32] @ W2chunk[32x128] ----
#pragma unroll
        for (int s = 0; s < 2; ++s) {
            uint32_t hh0[4], hh1[4], hl0[4], hl1[4];
            ldm4(hB0 + s * 32, hh0);
            ldm4(hB1 + s * 32, hh1);
            ldm4(hB0 + (SM_HLO - SM_HHI) + s * 32, hl0);
            ldm4(hB1 + (SM_HLO - SM_HHI) + s * 32, hl1);
#pragma unroll
            for (int p = 0; p < 4; ++p) {
                uint32_t bh[4], bl[4];
                ldm4(w2B[p] + s * 32, bh);
                ldm4(w2B[p] + (SM_W2LO - SM_W2HI) + s * 32, bl);
                float* a0 = acc2 + p * 8;
                float* a1 = acc2 + 32 + p * 8;
                mma_bf(a0 + 0, hh0, bh[0], bh[1]);
                mma_bf(a0 + 4, hh0, bh[2], bh[3]);
                mma_bf(a0 + 0, hh0, bl[0], bl[1]);
                mma_bf(a0 + 4, hh0, bl[2], bl[3]);
                mma_bf(a0 + 0, hl0, bh[0], bh[1]);
                mma_bf(a0 + 4, hl0, bh[2], bh[3]);
                mma_bf(a1 + 0, hh1, bh[0], bh[1]);
                mma_bf(a1 + 4, hh1, bh[2], bh[3]);
                mma_bf(a1 + 0, hh1, bl[0], bl[1]);
                mma_bf(a1 + 4, hh1, bl[2], bl[3]);
                mma_bf(a1 + 0, hl1, bh[0], bh[1]);
                mma_bf(a1 + 4, hl1, bh[2], bh[3]);
            }
        }
        __syncthreads();                         // W2 slab free
        if (c + 1 < 16) prefetch_w2(sb, c + 1, w2h, w2l, tid);
    }

    // ---- final epilogue: out = acc2 + b2 ----
#pragma unroll
    for (int mh = 0; mh < 2; ++mh) {
        int e0 = rowbase + wm * 32 + mh * 16 + rsub;
        int e1 = e0 + 8;
        int tgt0 = 0, tgt1 = 0;
        if (IS_EDGE) {
            tgt0 = (e0 < E) ? eidx[E + e0] : 0;
            tgt1 = (e1 < E) ? eidx[E + e1] : 0;
        }
#pragma unroll
        for (int p = 0; p < 4; ++p) {
#pragma unroll
            for (int t = 0; t < 2; ++t) {
                const float* ac = acc2 + mh * 32 + p * 8 + t * 4;
                int col = wn * 64 + p * 16 + t * 8 + cc;
                float ba = __ldg(b2 + col), bb = __ldg(b2 + col + 1);
                float v00 = ac[0] + ba, v01 = ac[1] + bb;
                float v10 = ac[2] + ba, v11 = ac[3] + bb;
                if (IS_EDGE) {
                    if (e0 < E) {
                        atomicAdd(out + (size_t)tgt0 * 128 + col, v00);
                        atomicAdd(out + (size_t)tgt0 * 128 + col + 1, v01);
                    }
                    if (e1 < E) {
                        atomicAdd(out + (size_t)tgt1 * 128 + col, v10);
                        atomicAdd(out + (size_t)tgt1 * 128 + col + 1, v11);
                    }
                } else {
                    if (e0 < M) *(float2*)(out + (size_t)e0 * 128 + col) = make_float2(v00, v01);
                    if (e1 < M) *(float2*)(out + (size_t)e1 * 128 + col) = make_float2(v10, v11);
                }
            }
        }
    }
}

extern "C" void kernel_launch(void* const* d_in, const int* in_sizes, int n_in,
                              void* d_out, int out_size) {
    const float* x   = (const float*)d_in[0];
    const int* eidx  = (const int*)d_in[2];   // JAX demotes int64 -> int32
    const float* W1m = (const float*)d_in[3];
    const float* b1m = (const float*)d_in[4];
    const float* W2m = (const float*)d_in[5];
    const float* b2m = (const float*)d_in[6];
    const float* W1u = (const float*)d_in[7];
    const float* b1u = (const float*)d_in[8];
    const float* W2u = (const float*)d_in[9];
    const float* b2u = (const float*)d_in[10];
    float* out = (float*)d_out;

    int N = in_sizes[0] / 128;
    int E = in_sizes[2] / 2;

    float* agg; cudaGetSymbolAddress((void**)&agg, g_agg);
    __nv_bfloat16 *w1mh, *w1ml, *w2mh, *w2ml, *w1uh, *w1ul, *w2uh, *w2ul;
    cudaGetSymbolAddress((void**)&w1mh, g_w1m_hi);
    cudaGetSymbolAddress((void**)&w1ml, g_w1m_lo);
    cudaGetSymbolAddress((void**)&w2mh, g_w2m_hi);
    cudaGetSymbolAddress((void**)&w2ml, g_w2m_lo);
    cudaGetSymbolAddress((void**)&w1uh, g_w1u_hi);
    cudaGetSymbolAddress((void**)&w1ul, g_w1u_lo);
    cudaGetSymbolAddress((void**)&w2uh, g_w2u_hi);
    cudaGetSymbolAddress((void**)&w2ul, g_w2u_lo);

    cudaFuncSetAttribute((const void*)mlp_mma<true>,
                         cudaFuncAttributeMaxDynamicSharedMemorySize, SM_TOTAL);
    cudaFuncSetAttribute((const void*)mlp_mma<false>,
                         cudaFuncAttributeMaxDynamicSharedMemorySize, SM_TOTAL);

    int n4 = (N * 128) / 4;
    zero_agg_kernel<<<(n4 + 255) / 256, 256>>>(agg, n4);
    prep_w1<<<512, 256>>>(W1m, w1mh, w1ml);
    prep_w2<<<256, 256>>>(W2m, w2mh, w2ml);
    prep_w1<<<512, 256>>>(W1u, w1uh, w1ul);
    prep_w2<<<256, 256>>>(W2u, w2uh, w2ul);

    mlp_mma<true><<<(E + ROWS - 1) / ROWS, NT, SM_TOTAL>>>(
        x, x, eidx, w1mh, w1ml, w2mh, w2ml, b1m, b2m, agg, E, E);

    mlp_mma<false><<<(N + ROWS - 1) / ROWS, NT, SM_TOTAL>>>(
        x, agg, nullptr, w1uh, w1ul, w2uh, w2ul, b1u, b2u, out, N, 0);
}

// round 7
// speedup vs baseline: 4.6037x; 1.5814x over previous
#include <cuda_runtime.h>
#include <cuda_fp16.h>
#include <cstdint>

#define NT 256
#define ROWS 128
#define NCHUNK 8
// smem byte offsets
#define SM_A     0        // 128 rows x 264 fp16 (row stride 528B), k=256 used
#define SM_W1HI  67584    // 64 n-rows x 264 k fp16
#define SM_W1LO  101376
#define SM_W2HI  135168   // 128 n-rows x 72 k fp16 (row stride 144B)
#define SM_W2LO  153600
#define SM_H     172032   // 128 rows x 72 fp16 (row stride 144B)
#define SM_TOTAL 190464

__device__ float g_agg[50000 * 128];
// weight images: fp16 hi/lo, chunk-contiguous
__device__ __align__(16) __half g_w1m_hi[8 * 64 * 264];
__device__ __align__(16) __half g_w1m_lo[8 * 64 * 264];
__device__ __align__(16) __half g_w2m_hi[8 * 128 * 72];
__device__ __align__(16) __half g_w2m_lo[8 * 128 * 72];
__device__ __align__(16) __half g_w1u_hi[8 * 64 * 264];
__device__ __align__(16) __half g_w1u_lo[8 * 64 * 264];
__device__ __align__(16) __half g_w2u_hi[8 * 128 * 72];
__device__ __align__(16) __half g_w2u_lo[8 * 128 * 72];

__device__ __forceinline__ uint32_t smem_u32(const void* p) {
    uint32_t a;
    asm("{ .reg .u64 t; cvta.to.shared.u64 t, %1; cvt.u32.u64 %0, t; }" : "=r"(a) : "l"(p));
    return a;
}
__device__ __forceinline__ void ldm4(uint32_t addr, uint32_t* r) {
    asm volatile("ldmatrix.sync.aligned.m8n8.x4.shared.b16 {%0,%1,%2,%3}, [%4];"
                 : "=r"(r[0]), "=r"(r[1]), "=r"(r[2]), "=r"(r[3]) : "r"(addr));
}
__device__ __forceinline__ void mma_f16(float* c, const uint32_t* a,
                                        uint32_t b0, uint32_t b1) {
    asm volatile(
        "mma.sync.aligned.m16n8k16.row.col.f32.f16.f16.f32 "
        "{%0,%1,%2,%3}, {%4,%5,%6,%7}, {%8,%9}, {%0,%1,%2,%3};"
        : "+f"(c[0]), "+f"(c[1]), "+f"(c[2]), "+f"(c[3])
        : "r"(a[0]), "r"(a[1]), "r"(a[2]), "r"(a[3]), "r"(b0), "r"(b1));
}
__device__ __forceinline__ void cp16(uint32_t dst, const void* src) {
    asm volatile("cp.async.cg.shared.global [%0], [%1], 16;" :: "r"(dst), "l"(src));
}
__device__ __forceinline__ uint32_t h2bits(__half2 v) {
    return *reinterpret_cast<uint32_t*>(&v);
}

__global__ void zero_agg_kernel(float* agg, int n4) {
    int i = blockIdx.x * blockDim.x + threadIdx.x;
    if (i < n4) ((float4*)agg)[i] = make_float4(0.f, 0.f, 0.f, 0.f);
}
// W1 [256k x 512n] -> [8 chunk(n64)][64 n][264 k] fp16 hi/lo
__global__ void prep_w1(const float* __restrict__ W, __half* hi, __half* lo) {
    int idx = blockIdx.x * blockDim.x + threadIdx.x;  // 131072
    int k = idx >> 9, n = idx & 511;
    float v = W[idx];
    __half h = __float2half_rn(v);
    int pos = (n >> 6) * 16896 + (n & 63) * 264 + k;
    hi[pos] = h;
    lo[pos] = __float2half_rn(v - __half2float(h));
}
// W2 [512k x 128n] -> [8 chunk(k64)][128 n][72 k] fp16 hi/lo
__global__ void prep_w2(const float* __restrict__ W, __half* hi, __half* lo) {
    int idx = blockIdx.x * blockDim.x + threadIdx.x;  // 65536
    int k = idx >> 7, n = idx & 127;
    float v = W[idx];
    __half h = __float2half_rn(v);
    int pos = (k >> 6) * 9216 + n * 72 + (k & 63);
    hi[pos] = h;
    lo[pos] = __float2half_rn(v - __half2float(h));
}

__device__ __forceinline__ void prefetch_w1(uint32_t sb, int c,
        const __half* w1h, const __half* w1l, int tid) {
    const char* sh = ((const char*)w1h) + c * 33792;
    const char* sl = ((const char*)w1l) + c * 33792;
#pragma unroll
    for (int j = 0; j < 9; ++j) {
        int idx = tid + j * NT;
        if (idx < 2112) {
            cp16(sb + SM_W1HI + idx * 16, sh + idx * 16);
            cp16(sb + SM_W1LO + idx * 16, sl + idx * 16);
        }
    }
    asm volatile("cp.async.commit_group;");
}
__device__ __forceinline__ void prefetch_w2(uint32_t sb, int c,
        const __half* w2h, const __half* w2l, int tid) {
    const char* sh = ((const char*)w2h) + c * 18432;
    const char* sl = ((const char*)w2l) + c * 18432;
#pragma unroll
    for (int j = 0; j < 5; ++j) {
        int idx = tid + j * NT;
        if (idx < 1152) {
            cp16(sb + SM_W2HI + idx * 16, sh + idx * 16);
            cp16(sb + SM_W2LO + idx * 16, sl + idx * 16);
        }
    }
    asm volatile("cp.async.commit_group;");
}

// Fused 2-layer MLP, 128 rows/CTA, fp16 A-single / W hi+lo 2-term mma.sync.
// Warps: 4m x 2n; GEMM1 chunk N=64 (warp n32); GEMM2 N=128 (warp n64).
template <bool IS_EDGE>
__global__ __launch_bounds__(NT, 1)
void mlp_mma(const float* __restrict__ x, const float* __restrict__ second,
             const int* __restrict__ eidx,
             const __half* __restrict__ w1h, const __half* __restrict__ w1l,
             const __half* __restrict__ w2h, const __half* __restrict__ w2l,
             const float* __restrict__ b1, const float* __restrict__ b2,
             float* __restrict__ out, int M, int E) {
    extern __shared__ __align__(16) unsigned char smem[];
    const uint32_t sb = smem_u32(smem);
    const int tid = threadIdx.x;
    const int lane = tid & 31;
    const int wid = tid >> 5;
    const int wm = wid & 3, wn = wid >> 2;   // 4 m-warps x 2 n-warps
    const int rowbase = blockIdx.x * ROWS;

    // chunk-0 weights in flight ASAP (commit order: W1 then W2)
    prefetch_w1(sb, 0, w1h, w1l, tid);
    prefetch_w2(sb, 0, w2h, w2l, tid);

    // ---- gather A = [feat_i(128) | feat_j(128)] -> fp16 smem ----
    {
        int r = tid >> 1, half = tid & 1;
        int row = rowbase + r;
        const float* src;
        if (IS_EDGE) {
            int e = (row < E) ? row : 0;
            int node = half ? eidx[e] : eidx[E + e];   // half0 = i, half1 = j
            src = x + (size_t)node * 128;
        } else {
            int rr = (row < M) ? row : 0;
            src = (half ? second : x) + (size_t)rr * 128;
        }
        uint32_t abase = sb + SM_A + (uint32_t)(r * 528 + half * 256);
#pragma unroll
        for (int jj = 0; jj < 32; ++jj) {
            float4 v = *(const float4*)(src + jj * 4);
            uint32_t h0 = h2bits(__float22half2_rn(make_float2(v.x, v.y)));
            uint32_t h1 = h2bits(__float22half2_rn(make_float2(v.z, v.w)));
            asm volatile("st.shared.v2.b32 [%0], {%1,%2};"
                         :: "r"(abase + jj * 8), "r"(h0), "r"(h1) : "memory");
        }
    }

    // ldmatrix base addresses
    const uint32_t aB0 = sb + SM_A +
        (uint32_t)((wm * 32 + (lane & 15)) * 528 + ((lane >> 4) & 1) * 16);
    const uint32_t aB1 = aB0 + 16 * 528;
    const uint32_t bB0 = sb + SM_W1HI +
        (uint32_t)((wn * 32 + (lane & 7) + ((lane >> 4) & 1) * 8) * 528 +
                   ((lane >> 3) & 1) * 16);
    const uint32_t bB1 = bB0 + 16 * 528;
    const uint32_t hB0 = sb + SM_H +
        (uint32_t)((wm * 32 + (lane & 15)) * 144 + ((lane >> 4) & 1) * 16);
    const uint32_t hB1 = hB0 + 16 * 144;
    uint32_t w2B[4];
#pragma unroll
    for (int p = 0; p < 4; ++p)
        w2B[p] = sb + SM_W2HI +
            (uint32_t)((wn * 64 + p * 16 + (lane & 7) + ((lane >> 4) & 1) * 8) * 144 +
                       ((lane >> 3) & 1) * 16);

    float acc2[64];
#pragma unroll
    for (int i = 0; i < 64; ++i) acc2[i] = 0.f;

    const int rsub = lane >> 2;        // 0..7
    const int cc = (lane & 3) * 2;

    for (int c = 0; c < NCHUNK; ++c) {
        asm volatile("cp.async.wait_group 1;");   // W1(c) ready
        __syncthreads();

        // ---- GEMM1: acc1[128 x 64chunk], K=256, D += Ah*W1h + Ah*W1l ----
        float acc1[32];
#pragma unroll
        for (int i = 0; i < 32; ++i) acc1[i] = 0.f;
#pragma unroll
        for (int s = 0; s < 16; ++s) {
            uint32_t ah0[4], ah1[4], bh0[4], bh1[4], bl0[4], bl1[4];
            ldm4(aB0 + s * 32, ah0);
            ldm4(aB1 + s * 32, ah1);
            ldm4(bB0 + s * 32, bh0);
            ldm4(bB1 + s * 32, bh1);
            ldm4(bB0 + (SM_W1LO - SM_W1HI) + s * 32, bl0);
            ldm4(bB1 + (SM_W1LO - SM_W1HI) + s * 32, bl1);
            mma_f16(acc1 + 0,  ah0, bh0[0], bh0[1]);
            mma_f16(acc1 + 4,  ah0, bh0[2], bh0[3]);
            mma_f16(acc1 + 8,  ah0, bh1[0], bh1[1]);
            mma_f16(acc1 + 12, ah0, bh1[2], bh1[3]);
            mma_f16(acc1 + 0,  ah0, bl0[0], bl0[1]);
            mma_f16(acc1 + 4,  ah0, bl0[2], bl0[3]);
            mma_f16(acc1 + 8,  ah0, bl1[0], bl1[1]);
            mma_f16(acc1 + 12, ah0, bl1[2], bl1[3]);
            mma_f16(acc1 + 16, ah1, bh0[0], bh0[1]);
            mma_f16(acc1 + 20, ah1, bh0[2], bh0[3]);
            mma_f16(acc1 + 24, ah1, bh1[0], bh1[1]);
            mma_f16(acc1 + 28, ah1, bh1[2], bh1[3]);
            mma_f16(acc1 + 16, ah1, bl0[0], bl0[1]);
            mma_f16(acc1 + 20, ah1, bl0[2], bl0[3]);
            mma_f16(acc1 + 24, ah1, bl1[0], bl1[1]);
            mma_f16(acc1 + 28, ah1, bl1[2], bl1[3]);
        }

        // ---- epilogue: relu(acc1 + b1) -> fp16 H smem (hi only) ----
#pragma unroll
        for (int im = 0; im < 2; ++im) {
#pragma unroll
            for (int nq = 0; nq < 4; ++nq) {
                const float* ac = acc1 + im * 16 + nq * 4;
                int gcol = c * 64 + wn * 32 + nq * 8 + cc;
                float ba = __ldg(b1 + gcol), bb = __ldg(b1 + gcol + 1);
                float v00 = fmaxf(ac[0] + ba, 0.f);
                float v01 = fmaxf(ac[1] + bb, 0.f);
                float v10 = fmaxf(ac[2] + ba, 0.f);
                float v11 = fmaxf(ac[3] + bb, 0.f);
                uint32_t p0 = h2bits(__float22half2_rn(make_float2(v00, v01)));
                uint32_t p1 = h2bits(__float22half2_rn(make_float2(v10, v11)));
                int hcol = wn * 32 + nq * 8 + cc;
                int r0 = wm * 32 + im * 16 + rsub;
                uint32_t a0 = sb + SM_H + (uint32_t)(r0 * 144 + hcol * 2);
                asm volatile("st.shared.b32 [%0], %1;" :: "r"(a0), "r"(p0) : "memory");
                asm volatile("st.shared.b32 [%0], %1;" :: "r"(a0 + 8 * 144), "r"(p1) : "memory");
            }
        }
        __syncthreads();                         // H visible; W1 slab free

        if (c + 1 < NCHUNK) {
            prefetch_w1(sb, c + 1, w1h, w1l, tid);
            asm volatile("cp.async.wait_group 1;");   // W2(c) ready
        } else {
            asm volatile("cp.async.wait_group 0;");
        }
        __syncthreads();

        // ---- GEMM2: acc2 += Hh[128x64] @ (W2h+W2l)[64x128] ----
#pragma unroll
        for (int s = 0; s < 4; ++s) {
            uint32_t hh0[4], hh1[4];
            ldm4(hB0 + s * 32, hh0);
            ldm4(hB1 + s * 32, hh1);
#pragma unroll
            for (int p = 0; p < 4; ++p) {
                uint32_t bh[4], bl[4];
                ldm4(w2B[p] + s * 32, bh);
                ldm4(w2B[p] + (SM_W2LO - SM_W2HI) + s * 32, bl);
                float* a0 = acc2 + p * 8;
                float* a1 = acc2 + 32 + p * 8;
                mma_f16(a0 + 0, hh0, bh[0], bh[1]);
                mma_f16(a0 + 4, hh0, bh[2], bh[3]);
                mma_f16(a0 + 0, hh0, bl[0], bl[1]);
                mma_f16(a0 + 4, hh0, bl[2], bl[3]);
                mma_f16(a1 + 0, hh1, bh[0], bh[1]);
                mma_f16(a1 + 4, hh1, bh[2], bh[3]);
                mma_f16(a1 + 0, hh1, bl[0], bl[1]);
                mma_f16(a1 + 4, hh1, bl[2], bl[3]);
            }
        }
        __syncthreads();                         // W2 slab free
        if (c + 1 < NCHUNK) prefetch_w2(sb, c + 1, w2h, w2l, tid);
    }

    // ---- final epilogue: out = acc2 + b2 ----
#pragma unroll
    for (int im = 0; im < 2; ++im) {
        int e0 = rowbase + wm * 32 + im * 16 + rsub;
        int e1 = e0 + 8;
        int tgt0 = 0, tgt1 = 0;
        if (IS_EDGE) {
            tgt0 = (e0 < E) ? eidx[E + e0] : 0;
            tgt1 = (e1 < E) ? eidx[E + e1] : 0;
        }
#pragma unroll
        for (int p = 0; p < 4; ++p) {
#pragma unroll
            for (int t = 0; t < 2; ++t) {
                const float* ac = acc2 + im * 32 + p * 8 + t * 4;
                int col = wn * 64 + p * 16 + t * 8 + cc;
                float ba = __ldg(b2 + col), bb = __ldg(b2 + col + 1);
                float v00 = ac[0] + ba, v01 = ac[1] + bb;
                float v10 = ac[2] + ba, v11 = ac[3] + bb;
                if (IS_EDGE) {
                    if (e0 < E) {
                        atomicAdd(out + (size_t)tgt0 * 128 + col, v00);
                        atomicAdd(out + (size_t)tgt0 * 128 + col + 1, v01);
                    }
                    if (e1 < E) {
                        atomicAdd(out + (size_t)tgt1 * 128 + col, v10);
                        atomicAdd(out + (size_t)tgt1 * 128 + col + 1, v11);
                    }
                } else {
                    if (e0 < M) *(float2*)(out + (size_t)e0 * 128 + col) = make_float2(v00, v01);
                    if (e1 < M) *(float2*)(out + (size_t)e1 * 128 + col) = make_float2(v10, v11);
                }
            }
        }
    }
}

extern "C" void kernel_launch(void* const* d_in, const int* in_sizes, int n_in,
                              void* d_out, int out_size) {
    const float* x   = (const float*)d_in[0];
    const int* eidx  = (const int*)d_in[2];   // JAX demotes int64 -> int32
    const float* W1m = (const float*)d_in[3];
    const float* b1m = (const float*)d_in[4];
    const float* W2m = (const float*)d_in[5];
    const float* b2m = (const float*)d_in[6];
    const float* W1u = (const float*)d_in[7];
    const float* b1u = (const float*)d_in[8];
    const float* W2u = (const float*)d_in[9];
    const float* b2u = (const float*)d_in[10];
    float* out = (float*)d_out;

    int N = in_sizes[0] / 128;
    int E = in_sizes[2] / 2;

    float* agg; cudaGetSymbolAddress((void**)&agg, g_agg);
    __half *w1mh, *w1ml, *w2mh, *w2ml, *w1uh, *w1ul, *w2uh, *w2ul;
    cudaGetSymbolAddress((void**)&w1mh, g_w1m_hi);
    cudaGetSymbolAddress((void**)&w1ml, g_w1m_lo);
    cudaGetSymbolAddress((void**)&w2mh, g_w2m_hi);
    cudaGetSymbolAddress((void**)&w2ml, g_w2m_lo);
    cudaGetSymbolAddress((void**)&w1uh, g_w1u_hi);
    cudaGetSymbolAddress((void**)&w1ul, g_w1u_lo);
    cudaGetSymbolAddress((void**)&w2uh, g_w2u_hi);
    cudaGetSymbolAddress((void**)&w2ul, g_w2u_lo);

    cudaFuncSetAttribute((const void*)mlp_mma<true>,
                         cudaFuncAttributeMaxDynamicSharedMemorySize, SM_TOTAL);
    cudaFuncSetAttribute((const void*)mlp_mma<false>,
                         cudaFuncAttributeMaxDynamicSharedMemorySize, SM_TOTAL);

    int n4 = (N * 128) / 4;
    zero_agg_kernel<<<(n4 + 255) / 256, 256>>>(agg, n4);
    prep_w1<<<512, 256>>>(W1m, w1mh, w1ml);
    prep_w2<<<256, 256>>>(W2m, w2mh, w2ml);
    prep_w1<<<512, 256>>>(W1u, w1uh, w1ul);
    prep_w2<<<256, 256>>>(W2u, w2uh, w2ul);

    mlp_mma<true><<<(E + ROWS - 1) / ROWS, NT, SM_TOTAL>>>(
        x, x, eidx, w1mh, w1ml, w2mh, w2ml, b1m, b2m, agg, E, E);

    mlp_mma<false><<<(N + ROWS - 1) / ROWS, NT, SM_TOTAL>>>(
        x, agg, nullptr, w1uh, w1ul, w2uh, w2ul, b1u, b2u, out, N, 0);
}